// round 3
// baseline (speedup 1.0000x reference)
#include <cuda_runtime.h>

#define N_IN   128
#define N_HID  512
#define N_OUT  128
#define BATCH  128
#define LENGTH 1024
#define M_ROWS (BATCH * LENGTH)

#define OUT_LIST_OFF  67108864ull   // after hidden_list [128,1024,512]
#define OUT_FINAL_OFF 83886080ull   // after output_list [128,1024,128]

__device__ float    g_Weff[N_HID * N_IN];
__device__ float    g_beff[N_HID];
__device__ float    g_hcur[2][BATCH * N_HID];
__device__ unsigned g_cnt[8 * 32];

// ---------------- init: reset barrier counters, load h0 into ping buffer 0 --
__global__ void init_kernel(const float* __restrict__ h0) {
    int i = blockIdx.x * blockDim.x + threadIdx.x;
    if (i < 8 * 32) g_cnt[i] = 0u;
    if (i < BATCH * N_HID) g_hcur[0][i] = h0[i];
}

// ---------------- W_eff = W_ih @ W_in ; b_eff = W_ih@b_in + b_ih + b_hh -----
__global__ void weff_kernel(const float* __restrict__ Wih,
                            const float* __restrict__ Win,
                            const float* __restrict__ bin,
                            const float* __restrict__ bih,
                            const float* __restrict__ bhh) {
    const int j = blockIdx.x;   // 0..511
    const int i = threadIdx.x;  // 0..127
    __shared__ float sred[128];

    float acc = 0.0f;
    #pragma unroll 8
    for (int k = 0; k < N_HID; k++)
        acc = fmaf(Wih[j * N_HID + k], Win[k * N_IN + i], acc);
    g_Weff[j * N_IN + i] = acc;

    float accb = 0.0f;
    for (int k = i; k < N_HID; k += 128)
        accb = fmaf(Wih[j * N_HID + k], bin[k], accb);
    sred[i] = accb;
    __syncthreads();
    for (int st = 64; st > 0; st >>= 1) {
        if (i < st) sred[i] += sred[i + st];
        __syncthreads();
    }
    if (i == 0) g_beff[j] = sred[0] + bih[j] + bhh[j];
}

// ---------------- C[m][n] = sum_k A[m][k]*B[n][k] + bias[n] -----------------
// BM=BN=128, BK=8, 256 threads, 8x8 register tiles. M,N %128==0, K %8==0.
__global__ __launch_bounds__(256) void gemm_tn_bias(
    const float* __restrict__ A, const float* __restrict__ B,
    const float* __restrict__ bias, float* __restrict__ C,
    int M, int N, int K)
{
    __shared__ float As[8][132];
    __shared__ float Bs[8][132];

    const int tid = threadIdx.x;
    const int m0 = blockIdx.x * 128;
    const int n0 = blockIdx.y * 128;
    const int tx = tid & 15;
    const int ty = tid >> 4;
    const int lr = tid >> 1;
    const int lc = (tid & 1) << 2;

    float acc[8][8];
    #pragma unroll
    for (int i = 0; i < 8; i++)
        #pragma unroll
        for (int j = 0; j < 8; j++) acc[i][j] = 0.0f;

    const float* Ap = &A[(size_t)(m0 + lr) * K + lc];
    const float* Bp = &B[(size_t)(n0 + lr) * K + lc];

    for (int k0 = 0; k0 < K; k0 += 8) {
        float4 av = *(const float4*)&Ap[k0];
        float4 bv = *(const float4*)&Bp[k0];
        As[lc + 0][lr] = av.x; As[lc + 1][lr] = av.y;
        As[lc + 2][lr] = av.z; As[lc + 3][lr] = av.w;
        Bs[lc + 0][lr] = bv.x; Bs[lc + 1][lr] = bv.y;
        Bs[lc + 2][lr] = bv.z; Bs[lc + 3][lr] = bv.w;
        __syncthreads();

        #pragma unroll
        for (int kk = 0; kk < 8; kk++) {
            float4 a0 = *(const float4*)&As[kk][ty * 8];
            float4 a1 = *(const float4*)&As[kk][ty * 8 + 4];
            float4 b0 = *(const float4*)&Bs[kk][tx * 8];
            float4 b1 = *(const float4*)&Bs[kk][tx * 8 + 4];
            float ra[8] = {a0.x, a0.y, a0.z, a0.w, a1.x, a1.y, a1.z, a1.w};
            float rb[8] = {b0.x, b0.y, b0.z, b0.w, b1.x, b1.y, b1.z, b1.w};
            #pragma unroll
            for (int i = 0; i < 8; i++)
                #pragma unroll
                for (int j = 0; j < 8; j++)
                    acc[i][j] = fmaf(ra[i], rb[j], acc[i][j]);
        }
        __syncthreads();
    }

    float bs[8];
    #pragma unroll
    for (int j = 0; j < 8; j++) bs[j] = bias[n0 + tx * 8 + j];

    #pragma unroll
    for (int i = 0; i < 8; i++) {
        float* crow = &C[(size_t)(m0 + ty * 8 + i) * N + n0 + tx * 8];
        *(float4*)&crow[0] = make_float4(acc[i][0] + bs[0], acc[i][1] + bs[1],
                                         acc[i][2] + bs[2], acc[i][3] + bs[3]);
        *(float4*)&crow[4] = make_float4(acc[i][4] + bs[4], acc[i][5] + bs[5],
                                         acc[i][6] + bs[6], acc[i][7] + bs[7]);
    }
}

// ---------------- recurrence ------------------------------------------------
// 128 CTAs = 8 groups (16 batches each) x 16 slices (32 h-rows each).
// W_hh slice cached in SMEM for all steps; h ping-ponged through L2.
#define WPAD 516

__global__ __launch_bounds__(256, 1) void rec_kernel(
    const float* __restrict__ Whh, float* __restrict__ hidden,
    float* __restrict__ hfinal)
{
    extern __shared__ float sm[];
    float* W_s = sm;              // 32 x 516
    float* h_s = sm + 32 * WPAD;  // 16 x 516

    const int tid  = threadIdx.x;
    const int g    = blockIdx.x >> 4;
    const int s    = blockIdx.x & 15;
    const int row0 = s * 32;
    const int b0   = g * 16;

    for (int idx = tid; idx < 32 * 128; idx += 256) {
        int r  = idx >> 7;
        int k4 = (idx & 127) << 2;
        *(float4*)&W_s[r * WPAD + k4] =
            *(const float4*)&Whh[(size_t)(row0 + r) * N_HID + k4];
    }

    const int row = tid >> 3;   // 0..31
    const int bp  = tid & 7;    // 0..7 -> local batches 2bp, 2bp+1
    const int absrow = row0 + row;
    const float* wrow  = &W_s[row * WPAD];
    const float* hrow0 = &h_s[(2 * bp) * WPAD];
    const float* hrow1 = &h_s[(2 * bp + 1) * WPAD];

    unsigned* cnt = &g_cnt[g * 32];

    for (int t = 0; t < LENGTH; t++) {
        __syncthreads();  // protect h_s reuse + pair with barrier release
        const float* hc = g_hcur[t & 1];
        for (int idx = tid; idx < 16 * 128; idx += 256) {
            int bl = idx >> 7;
            int k4 = (idx & 127) << 2;
            *(float4*)&h_s[bl * WPAD + k4] =
                __ldcg((const float4*)&hc[(size_t)(b0 + bl) * N_HID + k4]);
        }
        __syncthreads();

        float a0 = 0.f, a1 = 0.f, a2 = 0.f, a3 = 0.f;
        #pragma unroll 4
        for (int k = 0; k < N_HID; k += 4) {
            float4 w  = *(const float4*)&wrow[k];
            float4 ha = *(const float4*)&hrow0[k];
            float4 hb = *(const float4*)&hrow1[k];
            a0 = fmaf(w.x, ha.x, fmaf(w.y, ha.y, a0));
            a2 = fmaf(w.z, ha.z, fmaf(w.w, ha.w, a2));
            a1 = fmaf(w.x, hb.x, fmaf(w.y, hb.y, a1));
            a3 = fmaf(w.z, hb.z, fmaf(w.w, hb.w, a3));
        }
        float va = a0 + a2, vb = a1 + a3;

        #pragma unroll
        for (int j = 0; j < 2; j++) {
            int bl = 2 * bp + j;
            int b  = b0 + bl;
            float hold = h_s[bl * WPAD + absrow];
            size_t off = ((size_t)b * LENGTH + t) * N_HID + absrow;
            float zv = hidden[off];                      // pre-pass Z, in place
            float hn = 0.9f * hold + 0.1f * fmaxf(zv + (j ? vb : va), 0.0f);
            hidden[off] = hn;                            // hidden_list
            __stcg(&g_hcur[(t + 1) & 1][(size_t)b * N_HID + absrow], hn);
            if (t == LENGTH - 1) hfinal[(size_t)b * N_HID + absrow] = hn;
        }

        __syncthreads();
        if (tid == 0) {
            __threadfence();                 // release our CTA's h stores
            atomicAdd(cnt, 1u);
            unsigned target = 16u * (unsigned)(t + 1);
            while (*((volatile unsigned*)cnt) < target) { }
            __threadfence();                 // acquire peers' h stores
        }
        // loop-top __syncthreads releases the CTA
    }
}

extern "C" void kernel_launch(void* const* d_in, const int* in_sizes, int n_in,
                              void* d_out, int out_size) {
    const float* u    = (const float*)d_in[0];
    const float* h0   = (const float*)d_in[1];
    const float* Win  = (const float*)d_in[2];
    const float* bin  = (const float*)d_in[3];
    const float* Wih  = (const float*)d_in[4];
    const float* bih  = (const float*)d_in[5];
    const float* Whh  = (const float*)d_in[6];
    const float* bhh  = (const float*)d_in[7];
    const float* Wout = (const float*)d_in[8];
    const float* bout = (const float*)d_in[9];

    float* out      = (float*)d_out;
    float* hidden   = out;                   // [128,1024,512]
    float* outlist  = out + OUT_LIST_OFF;    // [128,1024,128]
    float* hfinal   = out + OUT_FINAL_OFF;   // [128,512]

    init_kernel<<<256, 256>>>(h0);
    weff_kernel<<<N_HID, 128>>>(Wih, Win, bin, bih, bhh);

    // Z = U @ W_eff^T + b_eff  -> written into hidden region
    {
        float* dWeff; float* dbeff;
        cudaGetSymbolAddress((void**)&dWeff, g_Weff);
        cudaGetSymbolAddress((void**)&dbeff, g_beff);
        dim3 grid(M_ROWS / 128, N_HID / 128);
        gemm_tn_bias<<<grid, 256>>>(u, dWeff, dbeff, hidden,
                                    M_ROWS, N_HID, N_IN);
    }

    // recurrence (in-place on hidden region)
    {
        static int smem_set = 0;
        int smem = (32 * WPAD + 16 * WPAD) * sizeof(float);  // 99072 B
        if (!smem_set) {
            cudaFuncSetAttribute(rec_kernel,
                                 cudaFuncAttributeMaxDynamicSharedMemorySize,
                                 smem);
            smem_set = 1;
        }
        rec_kernel<<<128, 256, smem>>>(Whh, hidden, hfinal);
    }

    // output_list = hidden_list @ W_out^T + b_out
    {
        dim3 grid(M_ROWS / 128, N_OUT / 128);
        gemm_tn_bias<<<grid, 256>>>(hidden, Wout, bout, outlist,
                                    M_ROWS, N_OUT, N_HID);
    }
}

// round 4
// speedup vs baseline: 1.1367x; 1.1367x over previous
#include <cuda_runtime.h>
#include <cstdint>

#define N_IN   128
#define N_HID  512
#define N_OUT  128
#define BATCH  128
#define LENGTH 1024
#define M_ROWS (BATCH * LENGTH)

#define OUT_LIST_OFF  67108864ull   // after hidden_list [128,1024,512]
#define OUT_FINAL_OFF 83886080ull   // after output_list [128,1024,128]

__device__ float g_Weff[N_HID * N_IN];
__device__ float g_beff[N_HID];

// ---------------- W_eff = W_ih @ W_in ; b_eff = W_ih@b_in + b_ih + b_hh -----
__global__ void weff_kernel(const float* __restrict__ Wih,
                            const float* __restrict__ Win,
                            const float* __restrict__ bin,
                            const float* __restrict__ bih,
                            const float* __restrict__ bhh) {
    const int j = blockIdx.x;   // 0..511
    const int i = threadIdx.x;  // 0..127
    __shared__ float sred[128];

    float acc = 0.0f;
    #pragma unroll 8
    for (int k = 0; k < N_HID; k++)
        acc = fmaf(Wih[j * N_HID + k], Win[k * N_IN + i], acc);
    g_Weff[j * N_IN + i] = acc;

    float accb = 0.0f;
    for (int k = i; k < N_HID; k += 128)
        accb = fmaf(Wih[j * N_HID + k], bin[k], accb);
    sred[i] = accb;
    __syncthreads();
    for (int st = 64; st > 0; st >>= 1) {
        if (i < st) sred[i] += sred[i + st];
        __syncthreads();
    }
    if (i == 0) g_beff[j] = sred[0] + bih[j] + bhh[j];
}

// ---------------- C[m][n] = sum_k A[m][k]*B[n][k] + bias[n] -----------------
__global__ __launch_bounds__(256) void gemm_tn_bias(
    const float* __restrict__ A, const float* __restrict__ B,
    const float* __restrict__ bias, float* __restrict__ C,
    int M, int N, int K)
{
    __shared__ float As[8][132];
    __shared__ float Bs[8][132];

    const int tid = threadIdx.x;
    const int m0 = blockIdx.x * 128;
    const int n0 = blockIdx.y * 128;
    const int tx = tid & 15;
    const int ty = tid >> 4;
    const int lr = tid >> 1;
    const int lc = (tid & 1) << 2;

    float acc[8][8];
    #pragma unroll
    for (int i = 0; i < 8; i++)
        #pragma unroll
        for (int j = 0; j < 8; j++) acc[i][j] = 0.0f;

    const float* Ap = &A[(size_t)(m0 + lr) * K + lc];
    const float* Bp = &B[(size_t)(n0 + lr) * K + lc];

    for (int k0 = 0; k0 < K; k0 += 8) {
        float4 av = *(const float4*)&Ap[k0];
        float4 bv = *(const float4*)&Bp[k0];
        As[lc + 0][lr] = av.x; As[lc + 1][lr] = av.y;
        As[lc + 2][lr] = av.z; As[lc + 3][lr] = av.w;
        Bs[lc + 0][lr] = bv.x; Bs[lc + 1][lr] = bv.y;
        Bs[lc + 2][lr] = bv.z; Bs[lc + 3][lr] = bv.w;
        __syncthreads();

        #pragma unroll
        for (int kk = 0; kk < 8; kk++) {
            float4 a0 = *(const float4*)&As[kk][ty * 8];
            float4 a1 = *(const float4*)&As[kk][ty * 8 + 4];
            float4 b0 = *(const float4*)&Bs[kk][tx * 8];
            float4 b1 = *(const float4*)&Bs[kk][tx * 8 + 4];
            float ra[8] = {a0.x, a0.y, a0.z, a0.w, a1.x, a1.y, a1.z, a1.w};
            float rb[8] = {b0.x, b0.y, b0.z, b0.w, b1.x, b1.y, b1.z, b1.w};
            #pragma unroll
            for (int i = 0; i < 8; i++)
                #pragma unroll
                for (int j = 0; j < 8; j++)
                    acc[i][j] = fmaf(ra[i], rb[j], acc[i][j]);
        }
        __syncthreads();
    }

    float bs[8];
    #pragma unroll
    for (int j = 0; j < 8; j++) bs[j] = bias[n0 + tx * 8 + j];

    #pragma unroll
    for (int i = 0; i < 8; i++) {
        float* crow = &C[(size_t)(m0 + ty * 8 + i) * N + n0 + tx * 8];
        *(float4*)&crow[0] = make_float4(acc[i][0] + bs[0], acc[i][1] + bs[1],
                                         acc[i][2] + bs[2], acc[i][3] + bs[3]);
        *(float4*)&crow[4] = make_float4(acc[i][4] + bs[4], acc[i][5] + bs[5],
                                         acc[i][6] + bs[6], acc[i][7] + bs[7]);
    }
}

// ---------------- recurrence: 16 clusters x 8 CTAs, DSMEM h-exchange --------
// Cluster owns 8 batches. CTA rank r computes h rows [64r, 64r+64) for all 8
// batches, W_hh slice resident in SMEM, h (full 512 per batch) double-buffered
// in SMEM; new h pushed to all 8 peers via st.shared::cluster; one
// barrier.cluster per step.
#define WPAD 516
#define HBUF (8 * WPAD)   // floats per h buffer

__device__ __forceinline__ uint32_t smem_u32(const void* p) {
    uint32_t a;
    asm("{ .reg .u64 t; cvta.to.shared.u64 t, %1; cvt.u32.u64 %0, t; }"
        : "=r"(a) : "l"(p));
    return a;
}

__global__ __cluster_dims__(8, 1, 1) __launch_bounds__(256, 1)
void rec_kernel(const float* __restrict__ Whh, const float* __restrict__ h0,
                float* __restrict__ hidden, float* __restrict__ hfinal)
{
    extern __shared__ float sm[];
    float* W_s = sm;               // 64 x 516
    float* H   = sm + 64 * WPAD;   // 2 x 8 x 516 (double buffer)

    const int tid = threadIdx.x;
    uint32_t rank;
    asm("mov.u32 %0, %%cluster_ctarank;" : "=r"(rank));
    const int grp  = blockIdx.x >> 3;
    const int row0 = (int)rank * 64;
    const int b0   = grp * 8;

    // stage W_hh rows [row0, row0+64)
    for (int idx = tid; idx < 64 * 128; idx += 256) {
        int r = idx >> 7, k4 = (idx & 127) << 2;
        *(float4*)&W_s[r * WPAD + k4] =
            *(const float4*)&Whh[(size_t)(row0 + r) * N_HID + k4];
    }
    // stage h0 into buffer 0 (all 8 batches, full vectors) — local only
    for (int idx = tid; idx < 8 * 128; idx += 256) {
        int bl = idx >> 7, k4 = (idx & 127) << 2;
        *(float4*)&H[bl * WPAD + k4] =
            *(const float4*)&h0[(size_t)(b0 + bl) * N_HID + k4];
    }

    // warp covers 8 rows x 8 batches; thread: 2 rows, 1 batch
    const int w    = tid >> 5;
    const int lane = tid & 31;
    const int bl   = lane & 7;
    const int rA   = w * 8 + (lane >> 3);   // local row 0..63 (first of pair)
    const int rB   = rA + 4;
    const int b    = b0 + bl;
    const int absA = row0 + rA;
    const int absB = row0 + rB;
    const float* wrA = &W_s[rA * WPAD];
    const float* wrB = &W_s[rB * WPAD];

    // peer SMEM base addresses of H (hoisted mapa per rank)
    uint32_t Hbase = smem_u32(H);
    uint32_t peer[8];
    #pragma unroll
    for (int r = 0; r < 8; r++)
        asm("mapa.shared::cluster.u32 %0, %1, %2;"
            : "=r"(peer[r]) : "r"(Hbase), "r"(r));

    __syncthreads();   // W_s + H buf0 ready (local)

    for (int t = 0; t < LENGTH; t++) {
        const int p = t & 1;
        const int q = p ^ 1;
        const float* hv = &H[p * HBUF + bl * WPAD];

        size_t offA = ((size_t)b * LENGTH + t) * N_HID + absA;
        size_t offB = offA + 4;
        float zA = hidden[offA];     // pre-pass Z (in place), hides under GEMV
        float zB = hidden[offB];

        float a0 = 0.f, a1 = 0.f, c0 = 0.f, c1 = 0.f;
        #pragma unroll 8
        for (int k = 0; k < N_HID; k += 4) {
            float4 h4 = *(const float4*)&hv[k];
            float4 wa = *(const float4*)&wrA[k];
            float4 wb = *(const float4*)&wrB[k];
            a0 = fmaf(wa.x, h4.x, fmaf(wa.y, h4.y, a0));
            a1 = fmaf(wa.z, h4.z, fmaf(wa.w, h4.w, a1));
            c0 = fmaf(wb.x, h4.x, fmaf(wb.y, h4.y, c0));
            c1 = fmaf(wb.z, h4.z, fmaf(wb.w, h4.w, c1));
        }
        float vA = a0 + a1, vB = c0 + c1;

        float holdA = hv[absA];
        float holdB = hv[absB];
        float hnA = 0.9f * holdA + 0.1f * fmaxf(zA + vA, 0.0f);
        float hnB = 0.9f * holdB + 0.1f * fmaxf(zB + vB, 0.0f);

        hidden[offA] = hnA;          // hidden_list
        hidden[offB] = hnB;
        if (t == LENGTH - 1) {
            hfinal[(size_t)b * N_HID + absA] = hnA;
            hfinal[(size_t)b * N_HID + absB] = hnB;
        }

        // push new h to all 8 CTAs' buffer q (fire-and-forget DSMEM stores)
        uint32_t doffA = (uint32_t)((q * HBUF + bl * WPAD + absA) * 4);
        uint32_t doffB = doffA + 16;   // absB = absA + 4 floats
        #pragma unroll
        for (int r = 0; r < 8; r++) {
            asm volatile("st.shared::cluster.f32 [%0], %1;"
                         :: "r"(peer[r] + doffA), "f"(hnA) : "memory");
            asm volatile("st.shared::cluster.f32 [%0], %1;"
                         :: "r"(peer[r] + doffB), "f"(hnB) : "memory");
        }

        // cluster barrier: release our DSMEM stores, acquire peers'
        asm volatile("barrier.cluster.arrive.aligned;" ::: "memory");
        asm volatile("barrier.cluster.wait.aligned;"   ::: "memory");
    }
}

extern "C" void kernel_launch(void* const* d_in, const int* in_sizes, int n_in,
                              void* d_out, int out_size) {
    const float* u    = (const float*)d_in[0];
    const float* h0   = (const float*)d_in[1];
    const float* Win  = (const float*)d_in[2];
    const float* bin  = (const float*)d_in[3];
    const float* Wih  = (const float*)d_in[4];
    const float* bih  = (const float*)d_in[5];
    const float* Whh  = (const float*)d_in[6];
    const float* bhh  = (const float*)d_in[7];
    const float* Wout = (const float*)d_in[8];
    const float* bout = (const float*)d_in[9];

    float* out     = (float*)d_out;
    float* hidden  = out;                   // [128,1024,512]
    float* outlist = out + OUT_LIST_OFF;    // [128,1024,128]
    float* hfinal  = out + OUT_FINAL_OFF;   // [128,512]

    weff_kernel<<<N_HID, 128>>>(Wih, Win, bin, bih, bhh);

    // Z = U @ W_eff^T + b_eff -> written into hidden region
    {
        float* dWeff; float* dbeff;
        cudaGetSymbolAddress((void**)&dWeff, g_Weff);
        cudaGetSymbolAddress((void**)&dbeff, g_beff);
        dim3 grid(M_ROWS / 128, N_HID / 128);
        gemm_tn_bias<<<grid, 256>>>(u, dWeff, dbeff, hidden,
                                    M_ROWS, N_HID, N_IN);
    }

    // recurrence (in-place on hidden region)
    {
        static int smem_set = 0;
        int smem = (64 * WPAD + 2 * 8 * WPAD) * sizeof(float);  // 165120 B
        if (!smem_set) {
            cudaFuncSetAttribute(rec_kernel,
                                 cudaFuncAttributeMaxDynamicSharedMemorySize,
                                 smem);
            smem_set = 1;
        }
        rec_kernel<<<128, 256, smem>>>(Whh, h0, hidden, hfinal);
    }

    // output_list = hidden_list @ W_out^T + b_out
    {
        dim3 grid(M_ROWS / 128, N_OUT / 128);
        gemm_tn_bias<<<grid, 256>>>(hidden, Wout, bout, outlist,
                                    M_ROWS, N_OUT, N_HID);
    }
}

// round 5
// speedup vs baseline: 1.1608x; 1.0212x over previous
#include <cuda_runtime.h>
#include <cstdint>

#define N_IN   128
#define N_HID  512
#define N_OUT  128
#define BATCH  128
#define LENGTH 1024
#define M_ROWS (BATCH * LENGTH)

#define OUT_LIST_OFF  67108864ull   // after hidden_list [128,1024,512]
#define OUT_FINAL_OFF 83886080ull   // after output_list [128,1024,128]

__device__ float g_Weff[N_HID * N_IN];
__device__ float g_beff[N_HID];

// ---------------- W_eff = W_ih @ W_in ; b_eff = W_ih@b_in + b_ih + b_hh -----
__global__ void weff_kernel(const float* __restrict__ Wih,
                            const float* __restrict__ Win,
                            const float* __restrict__ bin,
                            const float* __restrict__ bih,
                            const float* __restrict__ bhh) {
    const int j = blockIdx.x;   // 0..511
    const int i = threadIdx.x;  // 0..127
    __shared__ float sred[128];

    float acc = 0.0f;
    #pragma unroll 8
    for (int k = 0; k < N_HID; k++)
        acc = fmaf(Wih[j * N_HID + k], Win[k * N_IN + i], acc);
    g_Weff[j * N_IN + i] = acc;

    float accb = 0.0f;
    for (int k = i; k < N_HID; k += 128)
        accb = fmaf(Wih[j * N_HID + k], bin[k], accb);
    sred[i] = accb;
    __syncthreads();
    for (int st = 64; st > 0; st >>= 1) {
        if (i < st) sred[i] += sred[i + st];
        __syncthreads();
    }
    if (i == 0) g_beff[j] = sred[0] + bih[j] + bhh[j];
}

// ---------------- C[m][n] = sum_k A[m][k]*B[n][k] + bias[n] -----------------
__global__ __launch_bounds__(256) void gemm_tn_bias(
    const float* __restrict__ A, const float* __restrict__ B,
    const float* __restrict__ bias, float* __restrict__ C,
    int M, int N, int K)
{
    __shared__ float As[8][132];
    __shared__ float Bs[8][132];

    const int tid = threadIdx.x;
    const int m0 = blockIdx.x * 128;
    const int n0 = blockIdx.y * 128;
    const int tx = tid & 15;
    const int ty = tid >> 4;
    const int lr = tid >> 1;
    const int lc = (tid & 1) << 2;

    float acc[8][8];
    #pragma unroll
    for (int i = 0; i < 8; i++)
        #pragma unroll
        for (int j = 0; j < 8; j++) acc[i][j] = 0.0f;

    const float* Ap = &A[(size_t)(m0 + lr) * K + lc];
    const float* Bp = &B[(size_t)(n0 + lr) * K + lc];

    for (int k0 = 0; k0 < K; k0 += 8) {
        float4 av = *(const float4*)&Ap[k0];
        float4 bv = *(const float4*)&Bp[k0];
        As[lc + 0][lr] = av.x; As[lc + 1][lr] = av.y;
        As[lc + 2][lr] = av.z; As[lc + 3][lr] = av.w;
        Bs[lc + 0][lr] = bv.x; Bs[lc + 1][lr] = bv.y;
        Bs[lc + 2][lr] = bv.z; Bs[lc + 3][lr] = bv.w;
        __syncthreads();

        #pragma unroll
        for (int kk = 0; kk < 8; kk++) {
            float4 a0 = *(const float4*)&As[kk][ty * 8];
            float4 a1 = *(const float4*)&As[kk][ty * 8 + 4];
            float4 b0 = *(const float4*)&Bs[kk][tx * 8];
            float4 b1 = *(const float4*)&Bs[kk][tx * 8 + 4];
            float ra[8] = {a0.x, a0.y, a0.z, a0.w, a1.x, a1.y, a1.z, a1.w};
            float rb[8] = {b0.x, b0.y, b0.z, b0.w, b1.x, b1.y, b1.z, b1.w};
            #pragma unroll
            for (int i = 0; i < 8; i++)
                #pragma unroll
                for (int j = 0; j < 8; j++)
                    acc[i][j] = fmaf(ra[i], rb[j], acc[i][j]);
        }
        __syncthreads();
    }

    float bs[8];
    #pragma unroll
    for (int j = 0; j < 8; j++) bs[j] = bias[n0 + tx * 8 + j];

    #pragma unroll
    for (int i = 0; i < 8; i++) {
        float* crow = &C[(size_t)(m0 + ty * 8 + i) * N + n0 + tx * 8];
        *(float4*)&crow[0] = make_float4(acc[i][0] + bs[0], acc[i][1] + bs[1],
                                         acc[i][2] + bs[2], acc[i][3] + bs[3]);
        *(float4*)&crow[4] = make_float4(acc[i][4] + bs[4], acc[i][5] + bs[5],
                                         acc[i][6] + bs[6], acc[i][7] + bs[7]);
    }
}

// ---------------- recurrence: 16 clusters x 8 CTAs, vectorized DSMEM push ---
// Cluster owns 8 batches. CTA rank r computes h rows [64r, 64r+64) for all 8
// batches (W_hh slice in SMEM). New h values staged locally (transposed to
// [batch][row]) then pushed to all 8 ranks' H buffers as float4 DSMEM stores.
// One barrier.cluster per step.
#define WPAD  516
#define HBUF  (8 * WPAD)            // floats per h ping buffer
#define SPAD  68                    // stage row stride (16B aligned, cf-free)
#define STAGE_OFF (64 * WPAD + 2 * HBUF)

__device__ __forceinline__ uint32_t smem_u32(const void* p) {
    uint32_t a;
    asm("{ .reg .u64 t; cvta.to.shared.u64 t, %1; cvt.u32.u64 %0, t; }"
        : "=r"(a) : "l"(p));
    return a;
}

__global__ __cluster_dims__(8, 1, 1) __launch_bounds__(256, 1)
void rec_kernel(const float* __restrict__ Whh, const float* __restrict__ h0,
                float* __restrict__ hidden, float* __restrict__ hfinal)
{
    extern __shared__ float sm[];
    float* W_s   = sm;                    // 64 x 516
    float* H     = sm + 64 * WPAD;        // 2 x 8 x 516 (ping-pong)
    float* stage = sm + STAGE_OFF;        // 8 x 68  [batch][row]

    const int tid = threadIdx.x;
    uint32_t rank;
    asm("mov.u32 %0, %%cluster_ctarank;" : "=r"(rank));
    const int grp  = blockIdx.x >> 3;
    const int row0 = (int)rank * 64;
    const int b0   = grp * 8;

    // stage W_hh rows [row0, row0+64)
    for (int idx = tid; idx < 64 * 128; idx += 256) {
        int r = idx >> 7, k4 = (idx & 127) << 2;
        *(float4*)&W_s[r * WPAD + k4] =
            *(const float4*)&Whh[(size_t)(row0 + r) * N_HID + k4];
    }
    // h0 into buffer 0 (all 8 batches, full vectors) — local
    for (int idx = tid; idx < 8 * 128; idx += 256) {
        int bl = idx >> 7, k4 = (idx & 127) << 2;
        *(float4*)&H[bl * WPAD + k4] =
            *(const float4*)&h0[(size_t)(b0 + bl) * N_HID + k4];
    }

    // warp covers 8 rows x 8 batches; thread: rows rA,rA+4 of one batch
    const int w    = tid >> 5;
    const int lane = tid & 31;
    const int bl   = lane & 7;
    const int rA   = w * 8 + (lane >> 3);    // 0..63 (first of pair)
    const int rB   = rA + 4;
    const int b    = b0 + bl;
    const int absA = row0 + rA;
    const int absB = row0 + rB;
    const float* wrA = &W_s[rA * WPAD];
    const float* wrB = &W_s[rB * WPAD];

    // hoisted peer SMEM base addresses of H
    uint32_t Hbase = smem_u32(H);
    uint32_t peer[8];
    #pragma unroll
    for (int r = 0; r < 8; r++)
        asm("mapa.shared::cluster.u32 %0, %1, %2;"
            : "=r"(peer[r]) : "r"(Hbase), "r"(r));

    // push-loop decomposition: idx = tid + 256*i over (rank, batch, chunk)
    const int pr  = tid >> 7;          // rank pair base (handled 2 iters: +0,+2,..)
    const int pbl = (tid >> 4) & 7;    // batch
    const int pc  = tid & 15;          // 16B chunk (4 rows)
    const uint32_t sSrc = smem_u32(&stage[pbl * SPAD + pc * 4]);
    const uint32_t dOffBase = (uint32_t)((pbl * WPAD + row0 + pc * 4) * 4);

    __syncthreads();   // W_s + H buf0 ready (local)

    for (int t = 0; t < LENGTH; t++) {
        const int p = t & 1;
        const int q = p ^ 1;
        const float* hv = &H[p * HBUF + bl * WPAD];

        size_t offA = ((size_t)b * LENGTH + t) * N_HID + absA;
        size_t offB = offA + 4;
        float zA = hidden[offA];     // pre-pass Z (in place); hides under GEMV
        float zB = hidden[offB];

        float a0 = 0.f, a1 = 0.f, c0 = 0.f, c1 = 0.f;
        #pragma unroll 8
        for (int k = 0; k < N_HID; k += 4) {
            float4 h4 = *(const float4*)&hv[k];
            float4 wa = *(const float4*)&wrA[k];
            float4 wb = *(const float4*)&wrB[k];
            a0 = fmaf(wa.x, h4.x, fmaf(wa.y, h4.y, a0));
            a1 = fmaf(wa.z, h4.z, fmaf(wa.w, h4.w, a1));
            c0 = fmaf(wb.x, h4.x, fmaf(wb.y, h4.y, c0));
            c1 = fmaf(wb.z, h4.z, fmaf(wb.w, h4.w, c1));
        }
        float vA = a0 + a1, vB = c0 + c1;

        float hnA = 0.9f * hv[absA] + 0.1f * fmaxf(zA + vA, 0.0f);
        float hnB = 0.9f * hv[absB] + 0.1f * fmaxf(zB + vB, 0.0f);

        hidden[offA] = hnA;          // hidden_list (overwrites consumed Z)
        hidden[offB] = hnB;
        if (t == LENGTH - 1) {
            hfinal[(size_t)b * N_HID + absA] = hnA;
            hfinal[(size_t)b * N_HID + absB] = hnB;
        }

        // stage results transposed to [batch][row] (conflict-free STS.32)
        stage[bl * SPAD + rA] = hnA;
        stage[bl * SPAD + rB] = hnB;
        __syncthreads();

        // push slice to all 8 ranks' buffer q as float4 (4 stores/thread)
        const uint32_t dOff = (uint32_t)(q * HBUF * 4) + dOffBase;
        #pragma unroll
        for (int i = 0; i < 4; i++) {
            int r = pr + i * 2;
            float4 v = *(const float4*)__cvta_shared_to_generic(sSrc);
            asm volatile("st.shared::cluster.v4.f32 [%0], {%1,%2,%3,%4};"
                         :: "r"(peer[r] + dOff),
                            "f"(v.x), "f"(v.y), "f"(v.z), "f"(v.w)
                         : "memory");
        }

        // cluster barrier: release our DSMEM stores, acquire peers'
        asm volatile("barrier.cluster.arrive.aligned;" ::: "memory");
        asm volatile("barrier.cluster.wait.aligned;"   ::: "memory");
    }
}

extern "C" void kernel_launch(void* const* d_in, const int* in_sizes, int n_in,
                              void* d_out, int out_size) {
    const float* u    = (const float*)d_in[0];
    const float* h0   = (const float*)d_in[1];
    const float* Win  = (const float*)d_in[2];
    const float* bin  = (const float*)d_in[3];
    const float* Wih  = (const float*)d_in[4];
    const float* bih  = (const float*)d_in[5];
    const float* Whh  = (const float*)d_in[6];
    const float* bhh  = (const float*)d_in[7];
    const float* Wout = (const float*)d_in[8];
    const float* bout = (const float*)d_in[9];

    float* out     = (float*)d_out;
    float* hidden  = out;                   // [128,1024,512]
    float* outlist = out + OUT_LIST_OFF;    // [128,1024,128]
    float* hfinal  = out + OUT_FINAL_OFF;   // [128,512]

    weff_kernel<<<N_HID, 128>>>(Wih, Win, bin, bih, bhh);

    // Z = U @ W_eff^T + b_eff -> written into hidden region
    {
        float* dWeff; float* dbeff;
        cudaGetSymbolAddress((void**)&dWeff, g_Weff);
        cudaGetSymbolAddress((void**)&dbeff, g_beff);
        dim3 grid(M_ROWS / 128, N_HID / 128);
        gemm_tn_bias<<<grid, 256>>>(u, dWeff, dbeff, hidden,
                                    M_ROWS, N_HID, N_IN);
    }

    // recurrence (in-place on hidden region)
    {
        static int smem_set = 0;
        int smem = (STAGE_OFF + 8 * SPAD) * sizeof(float);  // ~167.4 KB
        if (!smem_set) {
            cudaFuncSetAttribute(rec_kernel,
                                 cudaFuncAttributeMaxDynamicSharedMemorySize,
                                 smem);
            smem_set = 1;
        }
        rec_kernel<<<128, 256, smem>>>(Whh, h0, hidden, hfinal);
    }

    // output_list = hidden_list @ W_out^T + b_out
    {
        dim3 grid(M_ROWS / 128, N_OUT / 128);
        gemm_tn_bias<<<grid, 256>>>(hidden, Wout, bout, outlist,
                                    M_ROWS, N_OUT, N_HID);
    }
}